// round 15
// baseline (speedup 1.0000x reference)
#include <cuda_runtime.h>
#include <cuda_fp16.h>
#include <cuda_bf16.h>
#include <cstdint>

// Problem constants
#define SIGMA   16
#define P       33
#define Hh      256
#define Wn      256
#define Bn      4
#define Kn      64
#define Nn      (Bn * Kn)          // 256 keypoints per side
#define NPATCH  (2 * Nn * Bn)      // 2048 total patches
#define C1      32
#define O1      31                 // conv1 out spatial (961 positions)
#define C2      64
#define O2      15                 // conv2 out spatial (225 positions)
#define NPOS1   (O1 * O1)          // 961
#define NT1     121                // ceil(961/8)
#define NPOS2   (O2 * O2)          // 225
#define NT2     29                 // ceil(225/8)
#define OUTF    128
#define TOTALF  (Nn * Bn * OUTF)   // 131072

// conv1 GEMM: K padded 27 -> 48 (tap-major: k = tap*4 + ic, ic 0..3, ic3 = pad)
#define W1PAD   56                 // halves per w1 row (conflict-free A)
// conv2 GEMM: K = 288 (chunk = ks, within-chunk k permuted so B is contiguous)
#define K2      288
#define KS2     18
#define S2      40                 // h1t halves per position (stride 80B -> 8 mod 32 words)

// smem byte offsets
#define SM_H1T    0                        // 961*40*2 = 76880
#define SM_GAP    76880                    // 64*4
#define SM_SB2    77136                    // 64*4
#define SM_SB1    77392                    // 32*4
#define SM_P2OFF  77520                    // 232*4 = 928
#define SM_PATCH  78448                    // 1089*4*2 = 8712 -> 8720
#define SM_W1H    87168                    // 32*56*2 = 3584
#define SM_P1OFF  90752                    // 968*4 = 3872
#define SMEM_BYTES 94624

__device__ __half g_w1h[C1 * W1PAD];
__device__ uint4  g_w2a[4 * KS2 * 32];     // A fragments: [mtile][ks][lane] -> (a0,a1,a2,a3)
__device__ float  g_feat[(size_t)NPATCH * OUTF];
__device__ int    g_count;

__device__ __forceinline__ void mma16816(float& c0, float& c1, float& c2, float& c3,
                                         uint32_t a0, uint32_t a1, uint32_t a2, uint32_t a3,
                                         uint32_t b0, uint32_t b1) {
    asm volatile(
        "mma.sync.aligned.m16n8k16.row.col.f32.f16.f16.f32 "
        "{%0,%1,%2,%3}, {%4,%5,%6,%7}, {%8,%9}, {%0,%1,%2,%3};"
        : "+f"(c0), "+f"(c1), "+f"(c2), "+f"(c3)
        : "r"(a0), "r"(a1), "r"(a2), "r"(a3), "r"(b0), "r"(b1));
}

// within-chunk permutation: fragment row r -> logical ic offset (0..15)
__host__ __device__ __forceinline__ int permr(int r) {
    return (r & 1) | (((r >> 3) & 1) << 1) | (((r >> 1) & 3) << 2);
}

// ---------------------------------------------------------------------------
// Prep: w1 (tap-major, fp16, padded) + w2 A-fragments pre-swizzled per lane
// ---------------------------------------------------------------------------
__global__ __launch_bounds__(512) void prep_kernel(
    const float* __restrict__ w1, const float* __restrict__ w2)
{
    int t = blockIdx.x * 512 + threadIdx.x;
    const int N1 = C1 * W1PAD;                 // 1792
    const int N2 = 4 * KS2 * 32 * 4;           // 9216 u32 outputs
    if (t < N1) {
        int oc = t / W1PAD, k = t - oc * W1PAD;
        float v = 0.0f;
        if (k < 36) {
            int tap = k >> 2, ic = k & 3;
            if (ic < 3) v = w1[oc * 27 + ic * 9 + tap];
        }
        g_w1h[t] = __float2half(v);
    } else if (t < N1 + N2) {
        int u = t - N1;                        // ((mt*18+ks)*32+lane)*4 + q
        int q    = u & 3;
        int lane = (u >> 2) & 31;
        int ks   = (u >> 7) % KS2;
        int mt   = (u >> 7) / KS2;
        int g  = lane >> 2;
        int t4 = lane & 3;
        int oc = mt * 16 + g + (q & 1) * 8;
        int kbase = 2 * t4 + (q >> 1) * 8;     // fragment rows kbase, kbase+1
        int tap    = ks >> 1;
        int icbase = (ks & 1) * 16;
        float vlo = w2[oc * K2 + (icbase + permr(kbase)) * 9 + tap];
        float vhi = w2[oc * K2 + (icbase + permr(kbase + 1)) * 9 + tap];
        __half2 h = __floats2half2_rn(vlo, vhi);
        ((uint32_t*)g_w2a)[u] = *(uint32_t*)&h;
    }
}

// ---------------------------------------------------------------------------
// Fused: crop + conv1(HMMA) + conv2(HMMA) + GAP + linear + loss (last block).
// One block per patch.
// ---------------------------------------------------------------------------
__global__ __launch_bounds__(512, 2) void fused_kernel(
    const float* __restrict__ img_g, const float* __restrict__ img_s,
    const float* __restrict__ kp_g,  const float* __restrict__ kp_s,
    const float* __restrict__ b1,    const float* __restrict__ b2,
    const float* __restrict__ wl,    const float* __restrict__ bl,
    float* __restrict__ out)
{
    extern __shared__ char smraw[];
    __half*   h1t     = (__half*)(smraw + SM_H1T);    // [961][40] channel-last
    float*    gap     = (float*)(smraw + SM_GAP);
    float*    sb2     = (float*)(smraw + SM_SB2);
    float*    sb1     = (float*)(smraw + SM_SB1);
    uint32_t* p2off   = (uint32_t*)(smraw + SM_P2OFF);
    __half*   patch_t = (__half*)(smraw + SM_PATCH);  // [1089][4] channel-last
    __half*   sw1h    = (__half*)(smraw + SM_W1H);
    uint32_t* p1off   = (uint32_t*)(smraw + SM_P1OFF);
    const char* h1b   = smraw + SM_H1T;
    const char* ptb   = smraw + SM_PATCH;

    const int tid  = threadIdx.x;
    const int pidx = blockIdx.x;
    const int side = pidx >> 10;
    const int r    = pidx & 1023;
    const int n    = r >> 2;
    const int b    = r & 3;

    const float* kps = side ? kp_s : kp_g;
    const float* img = side ? img_s : img_g;

    const float kx = kps[n * 2 + 0] * 256.0f;
    const float ky = kps[n * 2 + 1] * 256.0f;
    int sx = (int)floorf(kx) - SIGMA;
    int sy = (int)floorf(ky) - SIGMA;
    sx = min(max(sx, 0), Wn - P);
    sy = min(max(sy, 0), Hh - P);

    // ---- stage: patch (fp16 channel-last), w1, bias, tables ----
    for (int t = tid; t < P * P; t += 512) {
        int y = t / P, x = t - y * P;
        size_t base = (((size_t)b * 3) * Hh + (sy + y)) * Wn + (sx + x);
        float v0 = img[base];
        float v1 = img[base + (size_t)Hh * Wn];
        float v2 = img[base + 2 * (size_t)Hh * Wn];
        __half2* dst = (__half2*)(patch_t + t * 4);
        dst[0] = __floats2half2_rn(v0, v1);
        dst[1] = __floats2half2_rn(v2, 0.0f);
    }
    {
        const uint4* s1 = (const uint4*)g_w1h;
        uint4* d1 = (uint4*)sw1h;
        for (int t = tid; t < (C1 * W1PAD * 2) / 16; t += 512) d1[t] = s1[t];
    }
    if (tid < C1) sb1[tid] = b1[tid];
    if (tid < C2) { sb2[tid] = b2[tid]; gap[tid] = 0.0f; }
    for (int t = tid; t < 968; t += 512) {
        int pp = min(t, NPOS1 - 1);
        p1off[t] = (uint32_t)((pp / O1) * P + (pp % O1));   // patch spatial (33-wide)
    }
    if (tid < 232) {
        int pp = min(tid, NPOS2 - 1);
        p2off[tid] = (uint32_t)((pp / O2) * (2 * O1) + (pp % O2) * 2);  // h1 position idx
    }
    __syncthreads();

    const int wid  = tid >> 5;
    const int lane = tid & 31;
    const int g    = lane >> 2;
    const int t4   = lane & 3;

    // ---- conv1 via HMMA: D[32 x 968] = W1[32 x 48] @ im2col(patch)[48 x 968] ----
    {
        const int mb      = (wid & 1) * 16;
        const int nslice  = wid >> 1;            // 0..7
        const int th      = t4 >> 1;
        const int icsel   = (t4 & 1) * 4;        // byte offset into 4-ch slot

        uint32_t A[3][4];
        const __half* a1b = sw1h + (mb + g) * W1PAD + t4 * 2;
        #pragma unroll
        for (int ks = 0; ks < 3; ks++) {
            A[ks][0] = *(const uint32_t*)(a1b + ks * 16);
            A[ks][1] = *(const uint32_t*)(a1b + ks * 16 + 8 * W1PAD);
            A[ks][2] = *(const uint32_t*)(a1b + ks * 16 + 8);
            A[ks][3] = *(const uint32_t*)(a1b + ks * 16 + 8 * W1PAD + 8);
        }
        uint32_t tsA[3], tsB[3];
        #pragma unroll
        for (int ks = 0; ks < 3; ks++) {
            int ta = ks * 4 + th;
            int tb = ks * 4 + 2 + th;
            tsA[ks] = (ta < 9) ? (uint32_t)((ta / 3) * P + ta % 3) : 0u;
            tsB[ks] = (tb < 9) ? (uint32_t)((tb / 3) * P + tb % 3) : 0u;
        }
        const float bias0 = sb1[mb + g];
        const float bias1 = sb1[mb + 8 + g];

        for (int j = 0; j < 16; j++) {
            int nt = nslice + 8 * j;
            if (nt >= NT1) break;
            uint32_t pb = p1off[nt * 8 + g] * 8u + (uint32_t)icsel;
            float c0 = bias0, c1 = bias0, c2 = bias1, c3 = bias1;
            #pragma unroll
            for (int ks = 0; ks < 3; ks++) {
                uint32_t b0 = *(const uint32_t*)(ptb + pb + tsA[ks] * 8u);
                uint32_t b1v = *(const uint32_t*)(ptb + pb + tsB[ks] * 8u);
                mma16816(c0, c1, c2, c3,
                         A[ks][0], A[ks][1], A[ks][2], A[ks][3], b0, b1v);
            }
            int p0 = nt * 8 + t4 * 2;
            if (p0 < NPOS1) {
                h1t[p0 * S2 + mb + g]     = __float2half(fmaxf(c0, 0.0f));
                h1t[p0 * S2 + mb + 8 + g] = __float2half(fmaxf(c2, 0.0f));
            }
            if (p0 + 1 < NPOS1) {
                h1t[(p0 + 1) * S2 + mb + g]     = __float2half(fmaxf(c1, 0.0f));
                h1t[(p0 + 1) * S2 + mb + 8 + g] = __float2half(fmaxf(c3, 0.0f));
            }
        }
    }
    __syncthreads();

    // ---- conv2 via HMMA: D[64 x 232] = W2[64 x 288] @ im2col(h1t)[288 x 232] ----
    // Warp = (mpair, nslice): 2 m-tiles share each B fragment (halved smem traffic,
    // 2 MMAs per LDS.64), 4 n-chunks -> 8 independent accumulator chains.
    {
        const int mpair  = wid & 1;       // mtiles {0,1} or {2,3}
        const int nslice = wid >> 1;      // 0..7
        const int mb0    = mpair * 32;    // oc base of mtile pair

        const float biasA0 = sb2[mb0 + g],      biasA1 = sb2[mb0 + 8 + g];
        const float biasB0 = sb2[mb0 + 16 + g], biasB1 = sb2[mb0 + 24 + g];

        float c[2][4][4];
        uint32_t pbyte[4];
        #pragma unroll
        for (int jj = 0; jj < 4; jj++) {
            int nt = nslice + 8 * jj;
            if (nt < NT2) {
                pbyte[jj] = p2off[nt * 8 + g] * (uint32_t)(S2 * 2) + (uint32_t)(t4 * 8);
                c[0][jj][0] = biasA0; c[0][jj][1] = biasA0;
                c[0][jj][2] = biasA1; c[0][jj][3] = biasA1;
                c[1][jj][0] = biasB0; c[1][jj][1] = biasB0;
                c[1][jj][2] = biasB1; c[1][jj][3] = biasB1;
            }
        }

        const uint4* aPtr0 = g_w2a + (size_t)(2 * mpair)     * KS2 * 32 + lane;
        const uint4* aPtr1 = g_w2a + (size_t)(2 * mpair + 1) * KS2 * 32 + lane;

        #pragma unroll 2
        for (int ks = 0; ks < KS2; ks++) {
            const uint4 A0 = __ldg(aPtr0 + ks * 32);
            const uint4 A1 = __ldg(aPtr1 + ks * 32);
            const int tap = ks >> 1;
            const uint32_t koff = (uint32_t)(((tap / 3) * O1 + tap % 3) * (S2 * 2)
                                             + (ks & 1) * 32);
            #pragma unroll
            for (int jj = 0; jj < 4; jj++) {
                int nt = nslice + 8 * jj;
                if (nt < NT2) {
                    const uint2 v = *(const uint2*)(h1b + pbyte[jj] + koff);
                    mma16816(c[0][jj][0], c[0][jj][1], c[0][jj][2], c[0][jj][3],
                             A0.x, A0.y, A0.z, A0.w, v.x, v.y);
                    mma16816(c[1][jj][0], c[1][jj][1], c[1][jj][2], c[1][jj][3],
                             A1.x, A1.y, A1.z, A1.w, v.x, v.y);
                }
            }
        }

        // epilogue: relu + masked GAP partials, reduce over t4 (cols), atomics
        float vA0 = 0.0f, vA1 = 0.0f, vB0 = 0.0f, vB1 = 0.0f;
        #pragma unroll
        for (int jj = 0; jj < 4; jj++) {
            int nt = nslice + 8 * jj;
            if (nt < NT2) {
                int pos0 = nt * 8 + t4 * 2;
                float m0 = (pos0     < NPOS2) ? 1.0f : 0.0f;
                float m1 = (pos0 + 1 < NPOS2) ? 1.0f : 0.0f;
                vA0 = fmaf(fmaxf(c[0][jj][0], 0.0f), m0, vA0);
                vA0 = fmaf(fmaxf(c[0][jj][1], 0.0f), m1, vA0);
                vA1 = fmaf(fmaxf(c[0][jj][2], 0.0f), m0, vA1);
                vA1 = fmaf(fmaxf(c[0][jj][3], 0.0f), m1, vA1);
                vB0 = fmaf(fmaxf(c[1][jj][0], 0.0f), m0, vB0);
                vB0 = fmaf(fmaxf(c[1][jj][1], 0.0f), m1, vB0);
                vB1 = fmaf(fmaxf(c[1][jj][2], 0.0f), m0, vB1);
                vB1 = fmaf(fmaxf(c[1][jj][3], 0.0f), m1, vB1);
            }
        }
        vA0 += __shfl_xor_sync(0xFFFFFFFF, vA0, 1);
        vA0 += __shfl_xor_sync(0xFFFFFFFF, vA0, 2);
        vA1 += __shfl_xor_sync(0xFFFFFFFF, vA1, 1);
        vA1 += __shfl_xor_sync(0xFFFFFFFF, vA1, 2);
        vB0 += __shfl_xor_sync(0xFFFFFFFF, vB0, 1);
        vB0 += __shfl_xor_sync(0xFFFFFFFF, vB0, 2);
        vB1 += __shfl_xor_sync(0xFFFFFFFF, vB1, 1);
        vB1 += __shfl_xor_sync(0xFFFFFFFF, vB1, 2);
        if (t4 == 0) {
            atomicAdd(&gap[mb0 + g],      vA0);
            atomicAdd(&gap[mb0 + 8 + g],  vA1);
            atomicAdd(&gap[mb0 + 16 + g], vB0);
            atomicAdd(&gap[mb0 + 24 + g], vB1);
        }
    }
    __syncthreads();

    // ---- linear 64 -> 128 ----
    const float inv = 1.0f / (float)NPOS2;
    if (tid < OUTF) {
        float f = __ldg(&bl[tid]);
        const float* wrow = wl + tid * C2;
        #pragma unroll
        for (int cc = 0; cc < C2; cc++) f = fmaf(gap[cc] * inv, __ldg(&wrow[cc]), f);
        g_feat[(size_t)pidx * OUTF + tid] = f;
    }

    // ---- loss: last block reduces mean((fg - fs)^2) (deterministic) ----
    __threadfence();
    __syncthreads();
    __shared__ int amLast;
    if (tid == 0) amLast = (atomicAdd(&g_count, 1) == NPATCH - 1);
    __syncthreads();
    if (amLast) {
        __threadfence();
        const float4* fg = (const float4*)g_feat;
        const float4* fs = (const float4*)(g_feat + TOTALF);
        float s = 0.0f;
        for (int i = tid; i < TOTALF / 4; i += 512) {
            float4 a = fg[i], c4 = fs[i];
            float d0 = a.x - c4.x, d1 = a.y - c4.y;
            float d2 = a.z - c4.z, d3 = a.w - c4.w;
            s += d0 * d0 + d1 * d1 + d2 * d2 + d3 * d3;
        }
        __shared__ float red[16];
        #pragma unroll
        for (int off = 16; off > 0; off >>= 1)
            s += __shfl_down_sync(0xFFFFFFFF, s, off);
        if (lane == 0) red[wid] = s;
        __syncthreads();
        if (tid == 0) {
            float t = 0.0f;
            #pragma unroll
            for (int w = 0; w < 16; w++) t += red[w];
            out[0] = t / (float)TOTALF;
            g_count = 0;                 // reset for graph replay
        }
    }
}

extern "C" void kernel_launch(void* const* d_in, const int* in_sizes, int n_in,
                              void* d_out, int out_size)
{
    const float* img_g = (const float*)d_in[0];
    const float* img_s = (const float*)d_in[1];
    const float* kp_g  = (const float*)d_in[2];
    const float* kp_s  = (const float*)d_in[3];
    const float* w1    = (const float*)d_in[4];
    const float* b1    = (const float*)d_in[5];
    const float* w2    = (const float*)d_in[6];
    const float* b2    = (const float*)d_in[7];
    const float* wl    = (const float*)d_in[8];
    const float* bl    = (const float*)d_in[9];
    float* out = (float*)d_out;

    static bool attr_set = false;
    if (!attr_set) {
        cudaFuncSetAttribute(fused_kernel,
                             cudaFuncAttributeMaxDynamicSharedMemorySize, SMEM_BYTES);
        attr_set = true;
    }

    prep_kernel<<<22, 512>>>(w1, w2);
    fused_kernel<<<NPATCH, 512, SMEM_BYTES>>>(img_g, img_s, kp_g, kp_s,
                                              b1, b2, wl, bl, out);
}

// round 17
// speedup vs baseline: 1.0821x; 1.0821x over previous
#include <cuda_runtime.h>
#include <cuda_fp16.h>
#include <cuda_bf16.h>
#include <cstdint>

// Problem constants
#define SIGMA   16
#define P       33
#define Hh      256
#define Wn      256
#define Bn      4
#define Kn      64
#define Nn      (Bn * Kn)          // 256 keypoints per side
#define NPATCH  (2 * Nn * Bn)      // 2048 total patches
#define C1      32
#define O1      31                 // conv1 out spatial (961 positions)
#define C2      64
#define O2      15                 // conv2 out spatial (225 positions)
#define NPOS1   (O1 * O1)          // 961
#define NT1     121                // ceil(961/8)
#define NPOS2   (O2 * O2)          // 225
#define NT2     29                 // ceil(225/8)
#define OUTF    128
#define TOTALF  (Nn * Bn * OUTF)   // 131072

// conv2 GEMM: K = 288 (chunk = ks, within-chunk k permuted so B is contiguous)
#define K2      288
#define KS2     18
#define S2      40                 // h1t halves per position (stride 80B -> 8 mod 32 words)

// smem byte offsets
#define SM_H1T    0                        // 961*40*2 = 76880
#define SM_GAP    76880                    // 64*4
#define SM_SB2    77136                    // 64*4
#define SM_SB1    77392                    // 32*4
#define SM_P2OFF  77520                    // 232*4 = 928
#define SM_PATCH  78448                    // 1089*4*2 = 8712 -> 8720
#define SM_P1OFF  87168                    // 968*4 = 3872
#define SMEM_BYTES 91040

__device__ uint4  g_w1a[2 * 3 * 32];       // conv1 A fragments: [mt][chunk][lane]
__device__ uint4  g_w2a[4 * KS2 * 32];     // conv2 A fragments: [mtile][ks][lane]
__device__ float  g_feat[(size_t)NPATCH * OUTF];
__device__ float  g_part[256];
__device__ int    g_count;

__device__ __forceinline__ void mma16816(float& c0, float& c1, float& c2, float& c3,
                                         uint32_t a0, uint32_t a1, uint32_t a2, uint32_t a3,
                                         uint32_t b0, uint32_t b1) {
    asm volatile(
        "mma.sync.aligned.m16n8k16.row.col.f32.f16.f16.f32 "
        "{%0,%1,%2,%3}, {%4,%5,%6,%7}, {%8,%9}, {%0,%1,%2,%3};"
        : "+f"(c0), "+f"(c1), "+f"(c2), "+f"(c3)
        : "r"(a0), "r"(a1), "r"(a2), "r"(a3), "r"(b0), "r"(b1));
}

// conv2 within-chunk permutation: fragment row r -> logical ic offset (0..15)
__host__ __device__ __forceinline__ int permr(int r) {
    return (r & 1) | (((r >> 3) & 1) << 1) | (((r >> 1) & 3) << 2);
}

// ---------------------------------------------------------------------------
// Prep: pre-swizzled fp16 A fragments for both GEMMs.
// conv1 perm: row r -> tap = chunk*4 + ((r>>1)&3), ic = (r&1) | ((r>>3)&1)<<1
//   => per-thread B fragment = one tap's contiguous 4-channel slot (LDS.64).
// ---------------------------------------------------------------------------
__global__ __launch_bounds__(512) void prep_kernel(
    const float* __restrict__ w1, const float* __restrict__ w2)
{
    int t = blockIdx.x * 512 + threadIdx.x;
    const int N1 = 2 * 3 * 32 * 4;             // 768 u32 (g_w1a)
    const int N2 = 4 * KS2 * 32 * 4;           // 9216 u32 (g_w2a)
    if (t < N1) {
        int q    = t & 3;
        int lane = (t >> 2) & 31;
        int chunk = (t >> 7) % 3;
        int mt    = (t >> 7) / 3;
        int g  = lane >> 2;
        int t4 = lane & 3;
        int oc  = mt * 16 + g + (q & 1) * 8;
        int tap = chunk * 4 + t4;
        int icb = (q >> 1) * 2;
        float vlo = (tap < 9 && icb     < 3) ? w1[oc * 27 + icb       * 9 + tap] : 0.0f;
        float vhi = (tap < 9 && icb + 1 < 3) ? w1[oc * 27 + (icb + 1) * 9 + tap] : 0.0f;
        __half2 h = __floats2half2_rn(vlo, vhi);
        ((uint32_t*)g_w1a)[t] = *(uint32_t*)&h;
    } else if (t < N1 + N2) {
        int u = t - N1;                        // ((mt*18+ks)*32+lane)*4 + q
        int q    = u & 3;
        int lane = (u >> 2) & 31;
        int ks   = (u >> 7) % KS2;
        int mt   = (u >> 7) / KS2;
        int g  = lane >> 2;
        int t4 = lane & 3;
        int oc = mt * 16 + g + (q & 1) * 8;
        int kbase = 2 * t4 + (q >> 1) * 8;
        int tap    = ks >> 1;
        int icbase = (ks & 1) * 16;
        float vlo = w2[oc * K2 + (icbase + permr(kbase)) * 9 + tap];
        float vhi = w2[oc * K2 + (icbase + permr(kbase + 1)) * 9 + tap];
        __half2 h = __floats2half2_rn(vlo, vhi);
        ((uint32_t*)g_w2a)[u] = *(uint32_t*)&h;
    }
}

// ---------------------------------------------------------------------------
// Fused: crop + conv1(HMMA) + conv2(HMMA) + GAP + linear. One block / patch.
// ---------------------------------------------------------------------------
__global__ __launch_bounds__(512, 2) void fused_kernel(
    const float* __restrict__ img_g, const float* __restrict__ img_s,
    const float* __restrict__ kp_g,  const float* __restrict__ kp_s,
    const float* __restrict__ b1,    const float* __restrict__ b2,
    const float* __restrict__ wl,    const float* __restrict__ bl)
{
    extern __shared__ char smraw[];
    __half*   h1t     = (__half*)(smraw + SM_H1T);    // [961][40] channel-last
    float*    gap     = (float*)(smraw + SM_GAP);
    float*    sb2     = (float*)(smraw + SM_SB2);
    float*    sb1     = (float*)(smraw + SM_SB1);
    uint32_t* p2off   = (uint32_t*)(smraw + SM_P2OFF);
    __half*   patch_t = (__half*)(smraw + SM_PATCH);  // [1089][4] channel-last
    uint32_t* p1off   = (uint32_t*)(smraw + SM_P1OFF);
    const char* h1b   = smraw + SM_H1T;
    const char* ptb   = smraw + SM_PATCH;

    const int tid  = threadIdx.x;
    const int pidx = blockIdx.x;
    const int side = pidx >> 10;
    const int r    = pidx & 1023;
    const int n    = r >> 2;
    const int b    = r & 3;

    const float* kps = side ? kp_s : kp_g;
    const float* img = side ? img_s : img_g;

    const float kx = kps[n * 2 + 0] * 256.0f;
    const float ky = kps[n * 2 + 1] * 256.0f;
    int sx = (int)floorf(kx) - SIGMA;
    int sy = (int)floorf(ky) - SIGMA;
    sx = min(max(sx, 0), Wn - P);
    sy = min(max(sy, 0), Hh - P);

    // ---- stage: patch (fp16 channel-last), bias, tables ----
    for (int t = tid; t < P * P; t += 512) {
        int y = t / P, x = t - y * P;
        size_t base = (((size_t)b * 3) * Hh + (sy + y)) * Wn + (sx + x);
        float v0 = img[base];
        float v1 = img[base + (size_t)Hh * Wn];
        float v2 = img[base + 2 * (size_t)Hh * Wn];
        __half2* dst = (__half2*)(patch_t + t * 4);
        dst[0] = __floats2half2_rn(v0, v1);
        dst[1] = __floats2half2_rn(v2, 0.0f);
    }
    if (tid < C1) sb1[tid] = b1[tid];
    if (tid < C2) { sb2[tid] = b2[tid]; gap[tid] = 0.0f; }
    for (int t = tid; t < 968; t += 512) {
        int pp = min(t, NPOS1 - 1);
        p1off[t] = (uint32_t)((pp / O1) * P + (pp % O1));   // patch spatial (33-wide)
    }
    if (tid < 232) {
        int pp = min(tid, NPOS2 - 1);
        p2off[tid] = (uint32_t)((pp / O2) * (2 * O1) + (pp % O2) * 2);  // h1 position idx
    }
    __syncthreads();

    const int wid  = tid >> 5;
    const int lane = tid & 31;
    const int g    = lane >> 2;
    const int t4   = lane & 3;

    // ---- conv1 via HMMA: D[32 x 968] = W1[32 x 48] @ im2col(patch)[48 x 968] ----
    // B fragment = one LDS.64 per chunk (permuted k: tap per t4, 4-ch contiguous).
    {
        const int mt      = wid & 1;
        const int mb      = mt * 16;
        const int nslice  = wid >> 1;            // 0..7

        const uint4* a1Ptr = g_w1a + (size_t)mt * 3 * 32 + lane;
        uint4 A0 = __ldg(a1Ptr);
        uint4 A1 = __ldg(a1Ptr + 32);
        uint4 A2 = __ldg(a1Ptr + 64);

        uint32_t tsp[3];
        #pragma unroll
        for (int chunk = 0; chunk < 3; chunk++) {
            int tap = chunk * 4 + t4;
            tsp[chunk] = (tap < 9) ? (uint32_t)(((tap / 3) * P + tap % 3) * 8) : 0u;
        }
        const float bias0 = sb1[mb + g];
        const float bias1 = sb1[mb + 8 + g];

        for (int j = 0; j < 16; j++) {
            int nt = nslice + 8 * j;
            if (nt >= NT1) break;
            uint32_t pb = p1off[nt * 8 + g] * 8u;
            float c0 = bias0, c1 = bias0, c2 = bias1, c3 = bias1;
            {
                const uint2 v0 = *(const uint2*)(ptb + pb + tsp[0]);
                mma16816(c0, c1, c2, c3, A0.x, A0.y, A0.z, A0.w, v0.x, v0.y);
                const uint2 v1 = *(const uint2*)(ptb + pb + tsp[1]);
                mma16816(c0, c1, c2, c3, A1.x, A1.y, A1.z, A1.w, v1.x, v1.y);
                const uint2 v2 = *(const uint2*)(ptb + pb + tsp[2]);
                mma16816(c0, c1, c2, c3, A2.x, A2.y, A2.z, A2.w, v2.x, v2.y);
            }
            int p0 = nt * 8 + t4 * 2;
            if (p0 < NPOS1) {
                h1t[p0 * S2 + mb + g]     = __float2half(fmaxf(c0, 0.0f));
                h1t[p0 * S2 + mb + 8 + g] = __float2half(fmaxf(c2, 0.0f));
            }
            if (p0 + 1 < NPOS1) {
                h1t[(p0 + 1) * S2 + mb + g]     = __float2half(fmaxf(c1, 0.0f));
                h1t[(p0 + 1) * S2 + mb + 8 + g] = __float2half(fmaxf(c3, 0.0f));
            }
        }
    }
    __syncthreads();

    // ---- conv2 via HMMA: D[64 x 232] = W2[64 x 288] @ im2col(h1t)[288 x 232] ----
    // Warp = (mpair, nslice): 2 m-tiles share each B LDS.64; A double-buffered LDG.
    {
        const int mpair  = wid & 1;       // mtiles {0,1} or {2,3}
        const int nslice = wid >> 1;      // 0..7
        const int mb0    = mpair * 32;

        const float biasA0 = sb2[mb0 + g],      biasA1 = sb2[mb0 + 8 + g];
        const float biasB0 = sb2[mb0 + 16 + g], biasB1 = sb2[mb0 + 24 + g];

        float c[2][4][4];
        uint32_t pbyte[4];
        #pragma unroll
        for (int jj = 0; jj < 4; jj++) {
            int nt = nslice + 8 * jj;
            if (nt < NT2) {
                pbyte[jj] = p2off[nt * 8 + g] * (uint32_t)(S2 * 2) + (uint32_t)(t4 * 8);
                c[0][jj][0] = biasA0; c[0][jj][1] = biasA0;
                c[0][jj][2] = biasA1; c[0][jj][3] = biasA1;
                c[1][jj][0] = biasB0; c[1][jj][1] = biasB0;
                c[1][jj][2] = biasB1; c[1][jj][3] = biasB1;
            }
        }

        const uint4* aPtr0 = g_w2a + (size_t)(2 * mpair)     * KS2 * 32 + lane;
        const uint4* aPtr1 = g_w2a + (size_t)(2 * mpair + 1) * KS2 * 32 + lane;

        uint4 A0 = __ldg(aPtr0);
        uint4 A1 = __ldg(aPtr1);
        #pragma unroll 2
        for (int ks = 0; ks < KS2; ks++) {
            uint4 An0, An1;
            if (ks < KS2 - 1) {
                An0 = __ldg(aPtr0 + (ks + 1) * 32);
                An1 = __ldg(aPtr1 + (ks + 1) * 32);
            }
            const int tap = ks >> 1;
            const uint32_t koff = (uint32_t)(((tap / 3) * O1 + tap % 3) * (S2 * 2)
                                             + (ks & 1) * 32);
            #pragma unroll
            for (int jj = 0; jj < 4; jj++) {
                int nt = nslice + 8 * jj;
                if (nt < NT2) {
                    const uint2 v = *(const uint2*)(h1b + pbyte[jj] + koff);
                    mma16816(c[0][jj][0], c[0][jj][1], c[0][jj][2], c[0][jj][3],
                             A0.x, A0.y, A0.z, A0.w, v.x, v.y);
                    mma16816(c[1][jj][0], c[1][jj][1], c[1][jj][2], c[1][jj][3],
                             A1.x, A1.y, A1.z, A1.w, v.x, v.y);
                }
            }
            A0 = An0; A1 = An1;
        }

        // epilogue: relu + masked GAP partials, reduce over t4 (cols), atomics
        float vA0 = 0.0f, vA1 = 0.0f, vB0 = 0.0f, vB1 = 0.0f;
        #pragma unroll
        for (int jj = 0; jj < 4; jj++) {
            int nt = nslice + 8 * jj;
            if (nt < NT2) {
                int pos0 = nt * 8 + t4 * 2;
                float m0 = (pos0     < NPOS2) ? 1.0f : 0.0f;
                float m1 = (pos0 + 1 < NPOS2) ? 1.0f : 0.0f;
                vA0 = fmaf(fmaxf(c[0][jj][0], 0.0f), m0, vA0);
                vA0 = fmaf(fmaxf(c[0][jj][1], 0.0f), m1, vA0);
                vA1 = fmaf(fmaxf(c[0][jj][2], 0.0f), m0, vA1);
                vA1 = fmaf(fmaxf(c[0][jj][3], 0.0f), m1, vA1);
                vB0 = fmaf(fmaxf(c[1][jj][0], 0.0f), m0, vB0);
                vB0 = fmaf(fmaxf(c[1][jj][1], 0.0f), m1, vB0);
                vB1 = fmaf(fmaxf(c[1][jj][2], 0.0f), m0, vB1);
                vB1 = fmaf(fmaxf(c[1][jj][3], 0.0f), m1, vB1);
            }
        }
        vA0 += __shfl_xor_sync(0xFFFFFFFF, vA0, 1);
        vA0 += __shfl_xor_sync(0xFFFFFFFF, vA0, 2);
        vA1 += __shfl_xor_sync(0xFFFFFFFF, vA1, 1);
        vA1 += __shfl_xor_sync(0xFFFFFFFF, vA1, 2);
        vB0 += __shfl_xor_sync(0xFFFFFFFF, vB0, 1);
        vB0 += __shfl_xor_sync(0xFFFFFFFF, vB0, 2);
        vB1 += __shfl_xor_sync(0xFFFFFFFF, vB1, 1);
        vB1 += __shfl_xor_sync(0xFFFFFFFF, vB1, 2);
        if (t4 == 0) {
            atomicAdd(&gap[mb0 + g],      vA0);
            atomicAdd(&gap[mb0 + 8 + g],  vA1);
            atomicAdd(&gap[mb0 + 16 + g], vB0);
            atomicAdd(&gap[mb0 + 24 + g], vB1);
        }
    }
    __syncthreads();

    // ---- linear 64 -> 128 ----
    const float inv = 1.0f / (float)NPOS2;
    if (tid < OUTF) {
        float f = __ldg(&bl[tid]);
        const float* wrow = wl + tid * C2;
        #pragma unroll
        for (int cc = 0; cc < C2; cc++) f = fmaf(gap[cc] * inv, __ldg(&wrow[cc]), f);
        g_feat[(size_t)pidx * OUTF + tid] = f;
    }
}

// ---------------------------------------------------------------------------
// loss = mean((fg - fs)^2), single kernel: 256 partials + last-block reduce
// ---------------------------------------------------------------------------
__global__ __launch_bounds__(256) void loss_kernel(float* __restrict__ out)
{
    float s = 0.0f;
    const float4* fg = (const float4*)g_feat;
    const float4* fs = (const float4*)(g_feat + TOTALF);
    for (int i = blockIdx.x * 256 + threadIdx.x; i < TOTALF / 4; i += 256 * 256) {
        float4 a = fg[i], c4 = fs[i];
        float d0 = a.x - c4.x, d1 = a.y - c4.y;
        float d2 = a.z - c4.z, d3 = a.w - c4.w;
        s += d0 * d0 + d1 * d1 + d2 * d2 + d3 * d3;
    }
    __shared__ float red[8];
    __shared__ int   amLast;
    #pragma unroll
    for (int off = 16; off > 0; off >>= 1)
        s += __shfl_down_sync(0xFFFFFFFF, s, off);
    int wid = threadIdx.x >> 5;
    int lid = threadIdx.x & 31;
    if (lid == 0) red[wid] = s;
    __syncthreads();
    if (threadIdx.x == 0) {
        float t = 0.0f;
        #pragma unroll
        for (int w = 0; w < 8; w++) t += red[w];
        g_part[blockIdx.x] = t;
        __threadfence();
        int old = atomicAdd(&g_count, 1);
        amLast = (old == gridDim.x - 1);
    }
    __syncthreads();
    if (amLast) {
        float v = g_part[threadIdx.x];
        #pragma unroll
        for (int off = 16; off > 0; off >>= 1)
            v += __shfl_down_sync(0xFFFFFFFF, v, off);
        if (lid == 0) red[wid] = v;
        __syncthreads();
        if (threadIdx.x == 0) {
            float t = 0.0f;
            #pragma unroll
            for (int w = 0; w < 8; w++) t += red[w];
            out[0] = t / (float)TOTALF;
            g_count = 0;                 // reset for graph replay
        }
    }
}

extern "C" void kernel_launch(void* const* d_in, const int* in_sizes, int n_in,
                              void* d_out, int out_size)
{
    const float* img_g = (const float*)d_in[0];
    const float* img_s = (const float*)d_in[1];
    const float* kp_g  = (const float*)d_in[2];
    const float* kp_s  = (const float*)d_in[3];
    const float* w1    = (const float*)d_in[4];
    const float* b1    = (const float*)d_in[5];
    const float* w2    = (const float*)d_in[6];
    const float* b2    = (const float*)d_in[7];
    const float* wl    = (const float*)d_in[8];
    const float* bl    = (const float*)d_in[9];
    float* out = (float*)d_out;

    static bool attr_set = false;
    if (!attr_set) {
        cudaFuncSetAttribute(fused_kernel,
                             cudaFuncAttributeMaxDynamicSharedMemorySize, SMEM_BYTES);
        attr_set = true;
    }

    prep_kernel<<<20, 512>>>(w1, w2);
    fused_kernel<<<NPATCH, 512, SMEM_BYTES>>>(img_g, img_s, kp_g, kp_s,
                                              b1, b2, wl, bl);
    loss_kernel<<<256, 256>>>(out);
}